// round 15
// baseline (speedup 1.0000x reference)
#include <cuda_runtime.h>
#include <cuda_fp16.h>
#include <cstdint>

#define DIM      4096
#define NPAIRS   2048
#define GRD      64
#define P_TILE   4                               // pairs staged per block
#define THREADS  512
#define SLOTS    2                               // pair-slots (2 pairs each)
#define BSTEP    (THREADS / SLOTS)               // 256 batch rows per iter
#define GRID_ELEMS (GRD * GRD)                   // 4096 cells per pair
#define SMEM_BYTES (P_TILE * GRID_ELEMS * 4)     // 64 KB (half2 dup-pair cells)
#define GSIZE    2                               // iterations per pipeline group

__global__ void __launch_bounds__(THREADS, 2)
pair_bilinear_kernel(const float* __restrict__ x,
                     const float* __restrict__ pairW,
                     const float* __restrict__ Y,
                     float* __restrict__ out,
                     int groups)
{
    extern __shared__ __half2 sY[];  // [P_TILE][64][64] : cell = {Y[r][c], Y[r][c+1]}

    const int p0 = blockIdx.x * P_TILE;
    const int tid = threadIdx.x;

    const int sl = tid & (SLOTS - 1);    // pair-slot (0..1) -> pairs 2sl,2sl+1
    const int bs = tid >> 1;             // batch sub-index (0..255)
    const int pA = p0 + 2 * sl;          // first pair of this thread

    // x: 4 consecutive floats per (b, slot) -> one float4
    const float4* __restrict__ xp =
        reinterpret_cast<const float4*>(x) + (size_t)bs * (DIM / 4) + (pA >> 1);
    const int XSTR = BSTEP * (DIM / 4);

    // ── Hoisted first x-group prefetch: overlaps Y staging below ─────────
    float4 xa[GSIZE];
    #pragma unroll
    for (int i = 0; i < GSIZE; i++) xa[i] = xp[i * XSTR];
    xp += GSIZE * XSTR;

    // ── Stage: duplicated-pair fp16 grid from fp32 Y (once per block) ────
    // vnext via lane+1 shfl: with i = tid + k*512, lanes with tid%16 == 15
    // (lanes 15, 31) are exactly the row-end quads (c4 == 15) whose vnext is
    // never consumed, so the shfl wrap value is harmless.
    {
        const float4* __restrict__ Yg =
            reinterpret_cast<const float4*>(Y) + p0 * (GRID_ELEMS / 4);
        uint4* __restrict__ sY4 = reinterpret_cast<uint4*>(sY);
        #pragma unroll
        for (int i = tid; i < P_TILE * GRID_ELEMS / 4; i += THREADS) {
            const float4 v = __ldcs(Yg + i);                 // stream Y, evict-first
            const float vnext = __shfl_down_sync(0xFFFFFFFFu, v.x, 1);
            __half2 h[4];
            h[0] = __floats2half2_rn(v.x, v.y);
            h[1] = __floats2half2_rn(v.y, v.z);
            h[2] = __floats2half2_rn(v.z, v.w);
            h[3] = __floats2half2_rn(v.w, vnext);            // garbage only when c4==15 (unread)
            sY4[i] = *reinterpret_cast<const uint4*>(h);     // STS.128, conflict-free
        }
    }
    __syncthreads();

    const float4 wA = *(reinterpret_cast<const float4*>(pairW) + pA);
    const float4 wB = *(reinterpret_cast<const float4*>(pairW) + pA + 1);

    const __half2* __restrict__ sA = sY + (2 * sl) * GRID_ELEMS;
    const __half2* __restrict__ sB = sA + GRID_ELEMS;

    float2* __restrict__ op =
        reinterpret_cast<float2*>(out + (size_t)bs * NPAIRS + pA);
    const int OSTR = BSTEP * (NPAIRS / 2);

    // ── Software-pipelined main loop (16 groups, whole batch) ────────────
    for (int gset = 0; gset < groups; ++gset) {
        float4 xb[GSIZE];
        if (gset + 1 < groups) {
            #pragma unroll
            for (int i = 0; i < GSIZE; i++) xb[i] = xp[i * XSTR];
            xp += GSIZE * XSTR;
        }

        __half2 tA[GSIZE], bA[GSIZE], tB[GSIZE], bB[GSIZE];
        float frA[GSIZE], fcA[GSIZE], frB[GSIZE], fcB[GSIZE];

        // Phase A: addresses + all 4*GSIZE gathers in flight
        #pragma unroll
        for (int i = 0; i < GSIZE; i++) {
            const float a0 = fmaf(xa[i].x, wA.x, xa[i].y * wA.z);
            const float a1 = fmaf(xa[i].x, wA.y, xa[i].y * wA.w);
            const float b0 = fmaf(xa[i].z, wB.x, xa[i].w * wB.z);
            const float b1 = fmaf(xa[i].z, wB.y, xa[i].w * wB.w);

            const float gA0 = fminf(fmaxf(a0 * 63.0f, 0.0f), 63.0f);
            const float gA1 = fminf(fmaxf(a1 * 63.0f, 0.0f), 63.0f);
            const float gB0 = fminf(fmaxf(b0 * 63.0f, 0.0f), 63.0f);
            const float gB1 = fminf(fmaxf(b1 * 63.0f, 0.0f), 63.0f);

            const int rA = min((int)gA0, 62), cA = min((int)gA1, 62);
            const int rB = min((int)gB0, 62), cB = min((int)gB1, 62);
            frA[i] = gA0 - (float)rA;  fcA[i] = gA1 - (float)cA;
            frB[i] = gB0 - (float)rB;  fcB[i] = gB1 - (float)cB;

            const int baseA = (rA << 6) + cA;
            const int baseB = (rB << 6) + cB;
            tA[i] = sA[baseA];  bA[i] = sA[baseA + GRD];
            tB[i] = sB[baseB];  bB[i] = sB[baseB + GRD];
        }

        // Phase B: blend + vectorized streaming store
        #pragma unroll
        for (int i = 0; i < GSIZE; i++) {
            const float2 ta = __half22float2(tA[i]);
            const float2 ba = __half22float2(bA[i]);
            const float2 tb = __half22float2(tB[i]);
            const float2 bb = __half22float2(bB[i]);

            const float topA = fmaf(fcA[i], ta.y - ta.x, ta.x);
            const float botA = fmaf(fcA[i], ba.y - ba.x, ba.x);
            const float topB = fmaf(fcB[i], tb.y - tb.x, tb.x);
            const float botB = fmaf(fcB[i], bb.y - bb.x, bb.x);

            float2 o;
            o.x = fmaf(frA[i], botA - topA, topA);
            o.y = fmaf(frB[i], botB - topB, topB);
            __stcs(op, o);                       // STG.64, evict-first
            op += OSTR;
        }

        #pragma unroll
        for (int i = 0; i < GSIZE; i++) xa[i] = xb[i];
    }
}

extern "C" void kernel_launch(void* const* d_in, const int* in_sizes, int n_in,
                              void* d_out, int out_size)
{
    const float* x     = (const float*)d_in[0];
    const float* pairW = (const float*)d_in[1];
    const float* Y     = (const float*)d_in[2];
    float* out         = (float*)d_out;

    const int batch = in_sizes[0] / DIM;               // 8192
    const int groups = batch / (GSIZE * BSTEP);        // 8192 / 512 = 16

    cudaFuncSetAttribute(pair_bilinear_kernel,
                         cudaFuncAttributeMaxDynamicSharedMemorySize, SMEM_BYTES);

    dim3 grid(NPAIRS / P_TILE, 1);   // 512 persistent pair-tile blocks, 2/SM
    pair_bilinear_kernel<<<grid, THREADS, SMEM_BYTES>>>(x, pairW, Y, out, groups);
}

// round 16
// speedup vs baseline: 1.4387x; 1.4387x over previous
#include <cuda_runtime.h>
#include <cuda_fp16.h>
#include <cstdint>

#define DIM      4096
#define NPAIRS   2048
#define GRD      64
#define P_TILE   8                               // pairs staged per block
#define THREADS  1024
#define SLOTS    4                               // pair-slots (2 pairs each)
#define BSTEP    (THREADS / SLOTS)               // 256 batch rows per iter
#define GRID_ELEMS (GRD * GRD)                   // 4096 cells per pair
#define SMEM_BYTES (P_TILE * GRID_ELEMS * 4)     // 128 KB (half2 dup-pair cells)
#define GSIZE    2                               // iterations per pipeline group

__global__ void __launch_bounds__(THREADS, 1)
pair_bilinear_kernel(const float* __restrict__ x,
                     const float* __restrict__ pairW,
                     const float* __restrict__ Y,
                     float* __restrict__ out,
                     int groups)
{
    extern __shared__ __half2 sY[];  // [P_TILE][64][64] : cell = {Y[r][c], Y[r][c+1]}

    const int p0 = blockIdx.x * P_TILE;
    const int tid = threadIdx.x;

    const int sl = tid & (SLOTS - 1);    // pair-slot (0..3) -> pairs 2sl,2sl+1
    const int bs = tid >> 2;             // batch sub-index (0..255)
    const int pA = p0 + 2 * sl;          // first pair of this thread

    // x: 4 consecutive floats per (b, slot) -> one float4
    const float4* __restrict__ xp =
        reinterpret_cast<const float4*>(x) + (size_t)bs * (DIM / 4) + (pA >> 1);
    const int XSTR = BSTEP * (DIM / 4);

    // ── Hoisted first x-group prefetch: overlaps Y staging below ─────────
    float4 xa[GSIZE];
    #pragma unroll
    for (int i = 0; i < GSIZE; i++) xa[i] = __ldcs(xp + i * XSTR);
    xp += GSIZE * XSTR;

    // ── Stage: duplicated-pair fp16 grid from fp32 Y (once per block) ────
    {
        const float4* __restrict__ Yg =
            reinterpret_cast<const float4*>(Y) + p0 * (GRID_ELEMS / 4);
        uint4* __restrict__ sY4 = reinterpret_cast<uint4*>(sY);
        #pragma unroll
        for (int i = tid; i < P_TILE * GRID_ELEMS / 4; i += THREADS) {
            const float4 v = __ldcs(Yg + i);                 // stream Y, evict-first
            const float vnext = __shfl_down_sync(0xFFFFFFFFu, v.x, 1);
            __half2 h[4];
            h[0] = __floats2half2_rn(v.x, v.y);
            h[1] = __floats2half2_rn(v.y, v.z);
            h[2] = __floats2half2_rn(v.z, v.w);
            h[3] = __floats2half2_rn(v.w, vnext);            // garbage only when c4==15 (unread)
            sY4[i] = *reinterpret_cast<const uint4*>(h);     // STS.128, conflict-free
        }
    }
    __syncthreads();

    const float4 wA = *(reinterpret_cast<const float4*>(pairW) + pA);
    const float4 wB = *(reinterpret_cast<const float4*>(pairW) + pA + 1);

    const __half2* __restrict__ sA = sY + (2 * sl) * GRID_ELEMS;
    const __half2* __restrict__ sB = sA + GRID_ELEMS;

    float2* __restrict__ op =
        reinterpret_cast<float2*>(out + (size_t)bs * NPAIRS + pA);
    const int OSTR = BSTEP * (NPAIRS / 2);

    // ── Software-pipelined main loop (16 groups, whole batch) ────────────
    for (int gset = 0; gset < groups; ++gset) {
        float4 xb[GSIZE];
        if (gset + 1 < groups) {
            #pragma unroll
            for (int i = 0; i < GSIZE; i++) xb[i] = __ldcs(xp + i * XSTR);
            xp += GSIZE * XSTR;
        }

        __half2 tA[GSIZE], bA[GSIZE], tB[GSIZE], bB[GSIZE];
        float frA[GSIZE], fcA[GSIZE], frB[GSIZE], fcB[GSIZE];

        // Phase A: addresses + all 4*GSIZE gathers in flight
        // clamp(v,0,63) == __saturatef(v/63)*63 — .SAT folds into the FFMA
        #pragma unroll
        for (int i = 0; i < GSIZE; i++) {
            const float gA0 = __saturatef(fmaf(xa[i].x, wA.x, xa[i].y * wA.z)) * 63.0f;
            const float gA1 = __saturatef(fmaf(xa[i].x, wA.y, xa[i].y * wA.w)) * 63.0f;
            const float gB0 = __saturatef(fmaf(xa[i].z, wB.x, xa[i].w * wB.z)) * 63.0f;
            const float gB1 = __saturatef(fmaf(xa[i].z, wB.y, xa[i].w * wB.w)) * 63.0f;

            const int rA = min((int)gA0, 62), cA = min((int)gA1, 62);
            const int rB = min((int)gB0, 62), cB = min((int)gB1, 62);
            frA[i] = gA0 - (float)rA;  fcA[i] = gA1 - (float)cA;
            frB[i] = gB0 - (float)rB;  fcB[i] = gB1 - (float)cB;

            const int baseA = (rA << 6) + cA;
            const int baseB = (rB << 6) + cB;
            tA[i] = sA[baseA];  bA[i] = sA[baseA + GRD];
            tB[i] = sB[baseB];  bB[i] = sB[baseB + GRD];
        }

        // Phase B: blend + vectorized streaming store
        #pragma unroll
        for (int i = 0; i < GSIZE; i++) {
            const float2 ta = __half22float2(tA[i]);
            const float2 ba = __half22float2(bA[i]);
            const float2 tb = __half22float2(tB[i]);
            const float2 bb = __half22float2(bB[i]);

            const float topA = fmaf(fcA[i], ta.y - ta.x, ta.x);
            const float botA = fmaf(fcA[i], ba.y - ba.x, ba.x);
            const float topB = fmaf(fcB[i], tb.y - tb.x, tb.x);
            const float botB = fmaf(fcB[i], bb.y - bb.x, bb.x);

            float2 o;
            o.x = fmaf(frA[i], botA - topA, topA);
            o.y = fmaf(frB[i], botB - topB, topB);
            __stcs(op, o);                       // STG.64, evict-first
            op += OSTR;
        }

        #pragma unroll
        for (int i = 0; i < GSIZE; i++) xa[i] = xb[i];
    }
}

extern "C" void kernel_launch(void* const* d_in, const int* in_sizes, int n_in,
                              void* d_out, int out_size)
{
    const float* x     = (const float*)d_in[0];
    const float* pairW = (const float*)d_in[1];
    const float* Y     = (const float*)d_in[2];
    float* out         = (float*)d_out;

    const int batch = in_sizes[0] / DIM;               // 8192
    const int groups = batch / (GSIZE * BSTEP);        // 8192 / 512 = 16

    cudaFuncSetAttribute(pair_bilinear_kernel,
                         cudaFuncAttributeMaxDynamicSharedMemorySize, SMEM_BYTES);

    dim3 grid(NPAIRS / P_TILE, 1);   // 256 persistent pair-tile blocks (lockstep)
    pair_bilinear_kernel<<<grid, THREADS, SMEM_BYTES>>>(x, pairW, Y, out, groups);
}

// round 17
// speedup vs baseline: 1.4452x; 1.0045x over previous
#include <cuda_runtime.h>
#include <cuda_fp16.h>
#include <cstdint>

#define DIM      4096
#define NPAIRS   2048
#define GRD      64
#define P_TILE   8                               // pairs staged per block
#define THREADS  1024
#define SLOTS    4                               // pair-slots (2 pairs each)
#define BSTEP    (THREADS / SLOTS)               // 256 batch rows per iter
#define GRID_ELEMS (GRD * GRD)                   // 4096 cells per pair
#define SMEM_BYTES (P_TILE * GRID_ELEMS * 4)     // 128 KB (half2 dup-pair cells)
#define GSIZE    2                               // iterations per pipeline group
#define SCALE63  62.999937f                      // 63*(1-2^-20): (int)g <= 62 w/o min

__global__ void __launch_bounds__(THREADS, 1)
pair_bilinear_kernel(const float* __restrict__ x,
                     const float* __restrict__ pairW,
                     const float* __restrict__ Y,
                     float* __restrict__ out,
                     int groups)
{
    extern __shared__ __half2 sY[];  // [P_TILE][64][64] : cell = {Y[r][c], Y[r][c+1]}

    const int p0 = blockIdx.x * P_TILE;
    const int tid = threadIdx.x;

    const int sl = tid & (SLOTS - 1);    // pair-slot (0..3) -> pairs 2sl,2sl+1
    const int bs = tid >> 2;             // batch sub-index (0..255)
    const int pA = p0 + 2 * sl;          // first pair of this thread

    // x: 4 consecutive floats per (b, slot) -> one float4
    const float4* __restrict__ xp =
        reinterpret_cast<const float4*>(x) + (size_t)bs * (DIM / 4) + (pA >> 1);
    const int XSTR = BSTEP * (DIM / 4);

    // ── Hoisted first x-group prefetch: overlaps Y staging below ─────────
    float4 xa[GSIZE];
    #pragma unroll
    for (int i = 0; i < GSIZE; i++) xa[i] = __ldcs(xp + i * XSTR);
    xp += GSIZE * XSTR;

    // ── Stage: duplicated-pair fp16 grid from fp32 Y (once per block) ────
    {
        const float4* __restrict__ Yg =
            reinterpret_cast<const float4*>(Y) + p0 * (GRID_ELEMS / 4);
        uint4* __restrict__ sY4 = reinterpret_cast<uint4*>(sY);
        #pragma unroll
        for (int i = tid; i < P_TILE * GRID_ELEMS / 4; i += THREADS) {
            const float4 v = __ldcs(Yg + i);                 // stream Y, evict-first
            const float vnext = __shfl_down_sync(0xFFFFFFFFu, v.x, 1);
            __half2 h[4];
            h[0] = __floats2half2_rn(v.x, v.y);
            h[1] = __floats2half2_rn(v.y, v.z);
            h[2] = __floats2half2_rn(v.z, v.w);
            h[3] = __floats2half2_rn(v.w, vnext);            // garbage only when c4==15 (unread)
            sY4[i] = *reinterpret_cast<const uint4*>(h);     // STS.128, conflict-free
        }
    }
    __syncthreads();

    const float4 wA = *(reinterpret_cast<const float4*>(pairW) + pA);
    const float4 wB = *(reinterpret_cast<const float4*>(pairW) + pA + 1);

    const __half2* __restrict__ sA = sY + (2 * sl) * GRID_ELEMS;
    const __half2* __restrict__ sB = sA + GRID_ELEMS;

    float2* __restrict__ op =
        reinterpret_cast<float2*>(out + (size_t)bs * NPAIRS + pA);
    const int OSTR = BSTEP * (NPAIRS / 2);

    // ── Software-pipelined main loop (16 groups, whole batch) ────────────
    for (int gset = 0; gset < groups; ++gset) {
        float4 xb[GSIZE];
        if (gset + 1 < groups) {
            #pragma unroll
            for (int i = 0; i < GSIZE; i++) xb[i] = __ldcs(xp + i * XSTR);
            xp += GSIZE * XSTR;
        }

        __half2 tA[GSIZE], bA[GSIZE], tB[GSIZE], bB[GSIZE];
        float frA[GSIZE], fcA[GSIZE], frB[GSIZE], fcB[GSIZE];

        // Phase A: addresses + all 4*GSIZE gathers in flight.
        // SCALE63 guarantees (int)g <= 62 — no clamp needed after .SAT.
        #pragma unroll
        for (int i = 0; i < GSIZE; i++) {
            const float gA0 = __saturatef(fmaf(xa[i].x, wA.x, xa[i].y * wA.z)) * SCALE63;
            const float gA1 = __saturatef(fmaf(xa[i].x, wA.y, xa[i].y * wA.w)) * SCALE63;
            const float gB0 = __saturatef(fmaf(xa[i].z, wB.x, xa[i].w * wB.z)) * SCALE63;
            const float gB1 = __saturatef(fmaf(xa[i].z, wB.y, xa[i].w * wB.w)) * SCALE63;

            const float rAf = truncf(gA0), cAf = truncf(gA1);
            const float rBf = truncf(gB0), cBf = truncf(gB1);
            frA[i] = gA0 - rAf;  fcA[i] = gA1 - cAf;
            frB[i] = gB0 - rBf;  fcB[i] = gB1 - cBf;

            const int baseA = ((int)rAf << 6) + (int)cAf;
            const int baseB = ((int)rBf << 6) + (int)cBf;
            tA[i] = sA[baseA];  bA[i] = sA[baseA + GRD];
            tB[i] = sB[baseB];  bB[i] = sB[baseB + GRD];
        }

        // Phase B: packed fp16 row-blend (HFMA2) + fp32 column blend + store
        #pragma unroll
        for (int i = 0; i < GSIZE; i++) {
            const __half2 frA2 = __float2half2_rn(frA[i]);
            const __half2 frB2 = __float2half2_rn(frB[i]);
            const __half2 vA2 = __hfma2(frA2, __hsub2(bA[i], tA[i]), tA[i]);
            const __half2 vB2 = __hfma2(frB2, __hsub2(bB[i], tB[i]), tB[i]);
            const float2 vA = __half22float2(vA2);
            const float2 vB = __half22float2(vB2);

            float2 o;
            o.x = fmaf(fcA[i], vA.y - vA.x, vA.x);
            o.y = fmaf(fcB[i], vB.y - vB.x, vB.x);
            __stcs(op, o);                       // STG.64, evict-first
            op += OSTR;
        }

        #pragma unroll
        for (int i = 0; i < GSIZE; i++) xa[i] = xb[i];
    }
}

extern "C" void kernel_launch(void* const* d_in, const int* in_sizes, int n_in,
                              void* d_out, int out_size)
{
    const float* x     = (const float*)d_in[0];
    const float* pairW = (const float*)d_in[1];
    const float* Y     = (const float*)d_in[2];
    float* out         = (float*)d_out;

    const int batch = in_sizes[0] / DIM;               // 8192
    const int groups = batch / (GSIZE * BSTEP);        // 8192 / 512 = 16

    cudaFuncSetAttribute(pair_bilinear_kernel,
                         cudaFuncAttributeMaxDynamicSharedMemorySize, SMEM_BYTES);

    dim3 grid(NPAIRS / P_TILE, 1);   // 256 persistent pair-tile blocks (lockstep)
    pair_bilinear_kernel<<<grid, THREADS, SMEM_BYTES>>>(x, pairW, Y, out, groups);
}